// round 16
// baseline (speedup 1.0000x reference)
#include <cuda_runtime.h>
#include <cstdint>

#define SEQ    197
#define BATCH  64
#define HID    768
#define NHEAD  12
#define HD     64
#define MTOT   (BATCH*SEQ)      // 12608
#define NUMREL 732
#define NK     200
#define SP     204
#define BPITCH 200
#define PBP    12
#define PBUFW  (2*16*PBP)

// ---------------- scratch -----------------------------------------------------
__device__ float g_q[MTOT*HID];
__device__ float g_k[MTOT*HID];
__device__ float g_v[MTOT*HID];
__device__ float g_bias[NHEAD*SEQ*BPITCH];
__device__ float g_atf[MTOT*HID];
__device__ float g_wtf[3*HID*HID];

// ---------------- helpers ----------------------------------------------------
__device__ __forceinline__ float f2tf(float f){
    uint32_t u; asm("cvt.rna.tf32.f32 %0, %1;" : "=r"(u) : "f"(f));
    return __uint_as_float(u);
}
__device__ __forceinline__ uint32_t f2tfu(float f){
    uint32_t u; asm("cvt.rna.tf32.f32 %0, %1;" : "=r"(u) : "f"(f));
    return u;
}
__device__ __forceinline__ void mma8(float* d, const uint32_t* a, const uint32_t* b){
    asm volatile("mma.sync.aligned.m16n8k8.row.col.f32.tf32.tf32.f32 "
        "{%0,%1,%2,%3}, {%4,%5,%6,%7}, {%8,%9}, {%0,%1,%2,%3};"
        : "+f"(d[0]), "+f"(d[1]), "+f"(d[2]), "+f"(d[3])
        : "r"(a[0]), "r"(a[1]), "r"(a[2]), "r"(a[3]), "r"(b[0]), "r"(b[1]));
}
__device__ __forceinline__ void cpa16(uint32_t dst, const void* src){
    asm volatile("cp.async.cg.shared.global [%0], [%1], 16;" :: "r"(dst), "l"(src));
}
__device__ __forceinline__ void cpcommit(){ asm volatile("cp.async.commit_group;"); }
template<int N> __device__ __forceinline__ void cpwait(){
    asm volatile("cp.async.wait_group %0;" :: "n"(N));
}

// ---------------- tf32 pre-conversion -----------------------------------------
__global__ __launch_bounds__(256) void conv_tf32(const float* __restrict__ src,
                                                 float* __restrict__ dst, int n4){
    int i = blockIdx.x * blockDim.x + threadIdx.x;
    if(i >= n4) return;
    float4 v = ((const float4*)src)[i];
    v.x = f2tf(v.x); v.y = f2tf(v.y); v.z = f2tf(v.z); v.w = f2tf(v.w);
    ((float4*)dst)[i] = v;
}

// ---------------- QKV GEMM v6: 256 thr (4 warps/SMSP), cp.async 3-stage -------
// z=0:Q(+bq) z=1:K z=2:V(+bv). Block 128x128, 8 warps of 64x32, pre-converted tf32.
#define BM 128
#define BN 128
#define BK 16
#define APITCH 20
#define WPITCH 136
#define ASLOT (BM*APITCH)
#define WSLOT (BK*WPITCH)
#define GEMM_SMEM (3*(ASLOT+WSLOT)*4)   // 56,832 B

__global__ __launch_bounds__(256,2) void qkv_gemm(const float* __restrict__ bq,
                                                  const float* __restrict__ bv){
    extern __shared__ float sm[];
    float* Asb = sm;
    float* Wsb = sm + 3*ASLOT;

    const int z = blockIdx.z;
    const float* A = g_atf;
    const float* W = g_wtf + (size_t)z*HID*HID;
    const float* bias = (z == 0) ? bq : (z == 2 ? bv : nullptr);
    float* C = (z == 0) ? g_q : (z == 1 ? g_k : g_v);

    const int bm = blockIdx.x * BM, bn = blockIdx.y * BN;
    const int tid = threadIdx.x, wid = tid >> 5, lane = tid & 31;
    const int wm = (wid & 1) * 64;       // 2 warps tile M (64)
    const int wn = (wid >> 1) * 32;      // 4 warps tile N (32)
    const int g = lane >> 2, tg = lane & 3;

    const uint32_t sbase = (uint32_t)__cvta_generic_to_shared(sm);

    auto stage = [&](int slot, int kc){
        const int k0 = kc * BK;
        #pragma unroll
        for(int i=0;i<2;i++){
            int v = tid + i*256;
            int r = v >> 2, c = (v & 3) * 4;
            int grow = bm + r; if(grow >= MTOT) grow = MTOT-1;
            cpa16(sbase + (uint32_t)(slot*ASLOT + r*APITCH + c)*4u,
                  A + (size_t)grow*HID + k0 + c);
        }
        #pragma unroll
        for(int i=0;i<2;i++){
            int v = tid + i*256;
            int r = v >> 5, c = (v & 31) * 4;
            cpa16(sbase + (uint32_t)(3*ASLOT + slot*WSLOT + r*WPITCH + c)*4u,
                  W + (size_t)(k0+r)*HID + bn + c);
        }
    };

    float acc[4][4][4] = {};

    stage(0,0); cpcommit();
    stage(1,1); cpcommit();

    const int NC = HID / BK;   // 48
    for(int i=0;i<NC;i++){
        cpwait<1>();
        __syncthreads();
        if(i+2 < NC) stage((i+2)%3, i+2);
        cpcommit();

        const float* Ab = Asb + (i%3)*ASLOT;
        const float* Wb = Wsb + (i%3)*WSLOT;

        #pragma unroll
        for(int kk=0; kk<BK; kk+=8){
            uint32_t af[4][4], bf[4][2];
            #pragma unroll
            for(int mi=0;mi<4;mi++){
                const float* ap = Ab + (wm + mi*16 + g)*APITCH + kk + tg;
                af[mi][0] = __float_as_uint(ap[0]);
                af[mi][1] = __float_as_uint(ap[8*APITCH]);
                af[mi][2] = __float_as_uint(ap[4]);
                af[mi][3] = __float_as_uint(ap[8*APITCH+4]);
            }
            #pragma unroll
            for(int ni=0;ni<4;ni++){
                const float* wp = Wb + (kk+tg)*WPITCH + wn + ni*8 + g;
                bf[ni][0] = __float_as_uint(wp[0]);
                bf[ni][1] = __float_as_uint(wp[4*WPITCH]);
            }
            #pragma unroll
            for(int mi=0;mi<4;mi++)
                #pragma unroll
                for(int ni=0;ni<4;ni++)
                    mma8(acc[mi][ni], af[mi], bf[ni]);
        }
    }

    // ---- epilogue: bias + store ----
    #pragma unroll
    for(int mi=0;mi<4;mi++){
        #pragma unroll
        for(int ni=0;ni<4;ni++){
            int col = bn + wn + ni*8 + tg*2;
            float b0 = bias ? bias[col]   : 0.f;
            float b1 = bias ? bias[col+1] : 0.f;
            int r0 = bm + wm + mi*16 + g;
            if(r0 < MTOT)
                *(float2*)(C + (size_t)r0*HID + col) = make_float2(acc[mi][ni][0]+b0, acc[mi][ni][1]+b1);
            int r1 = r0 + 8;
            if(r1 < MTOT)
                *(float2*)(C + (size_t)r1*HID + col) = make_float2(acc[mi][ni][2]+b0, acc[mi][ni][3]+b1);
        }
    }
}

// ---------------- relative position bias (pitch 200) --------------------------
__global__ void build_bias(const float* __restrict__ table, float* __restrict__ bias){
    int qk = blockIdx.x * blockDim.x + threadIdx.x;
    if(qk >= SEQ*SEQ) return;
    int q = qk / SEQ, k = qk % SEQ;
    int idx;
    if(q == 0 && k == 0)      idx = NUMREL - 1;
    else if(q == 0)           idx = NUMREL - 3;
    else if(k == 0)           idx = NUMREL - 2;
    else {
        int i = q - 1, j = k - 1;
        int hi = i / 14, wi = i % 14;
        int hj = j / 14, wj = j % 14;
        idx = (hi - hj + 13) * 27 + (wi - wj + 13);
    }
    #pragma unroll
    for(int h = 0; h < NHEAD; h++)
        bias[(size_t)h*SEQ*BPITCH + q*BPITCH + k] = table[idx*NHEAD + h];
}

// ---------------- attention v5 (unchanged, verified 430.6) --------------------
#define ATTN_SMEM ((NK*HD + HD*SP + 16*PBUFW)*4)   // 128,000 B

__global__ __launch_bounds__(512,1) void attention(const float* __restrict__ Q,
                                                   const float* __restrict__ K,
                                                   const float* __restrict__ V,
                                                   const float* __restrict__ bias,
                                                   float* __restrict__ out){
    extern __shared__ float smA[];
    float* Ks = smA;
    float* Vt = smA + NK*HD;
    float* Pb = Vt + HD*SP;

    const int b = blockIdx.x / NHEAD, h = blockIdx.x % NHEAD;
    const int tid = threadIdx.x, wid = tid >> 5, lane = tid & 31;
    const int g = lane >> 2, tg = lane & 3;

    const float* Kb = K + (size_t)(b*SEQ)*HID + h*HD;
    const float* Vb = V + (size_t)(b*SEQ)*HID + h*HD;
    const float* Qb = Q + (size_t)(b*SEQ)*HID + h*HD;

    for(int v = tid; v < NK*16; v += 512){
        int s = v >> 4, t = v & 15;
        float4 kk = make_float4(0,0,0,0);
        if(s < SEQ) kk = *(const float4*)(Kb + (size_t)s*HID + 4*t);
        float* d = Ks + s*HD + 4*(t ^ (s & 7));
        d[0]=f2tf(kk.x); d[1]=f2tf(kk.y); d[2]=f2tf(kk.z); d[3]=f2tf(kk.w);
    }
    for(int v = tid; v < NK*HD; v += 512){
        int s = v >> 6, d = v & 63;
        float val = (s < SEQ) ? Vb[(size_t)s*HID + d] : 0.f;
        Vt[d*SP + s] = f2tf(val);
    }
    __syncthreads();

    if(wid < 13){
        const int q0 = wid*16;
        const int row0 = q0 + g, row1 = q0 + 8 + g;
        const int r0c = row0 < SEQ ? row0 : SEQ-1;
        const int r1c = row1 < SEQ ? row1 : SEQ-1;

        uint32_t aq[8][4];
        {
            const float* Q0 = Qb + (size_t)r0c*HID;
            const float* Q1 = Qb + (size_t)r1c*HID;
            #pragma unroll
            for(int ks=0; ks<8; ks++){
                aq[ks][0] = f2tfu(Q0[8*ks+tg  ] * 0.125f);
                aq[ks][1] = f2tfu(Q1[8*ks+tg  ] * 0.125f);
                aq[ks][2] = f2tfu(Q0[8*ks+tg+4] * 0.125f);
                aq[ks][3] = f2tfu(Q1[8*ks+tg+4] * 0.125f);
            }
        }

        const float* b0p = bias + (size_t)h*SEQ*BPITCH + (size_t)r0c*BPITCH;
        const float* b1p = bias + (size_t)h*SEQ*BPITCH + (size_t)r1c*BPITCH;
        float* myP = Pb + wid*PBUFW;

        float o[8][4] = {};
        float m0 = -1e30f, m1 = -1e30f, z0 = 0.f, z1 = 0.f;

        #pragma unroll
        for(int cc=0; cc<4; cc++){
            const int CNT  = (cc==0) ? 7 : 6;
            const int BASE = (cc==0) ? 0 : 7 + 6*(cc-1);

            float s[7][4];
            #pragma unroll
            for(int j=0;j<7;j++){ s[j][0]=0.f; s[j][1]=0.f; s[j][2]=0.f; s[j][3]=0.f; }

            #pragma unroll
            for(int j=0;j<CNT;j++){
                const int nt = BASE + j;
                const float* kr = Ks + (8*nt + g)*HD;
                #pragma unroll
                for(int ks=0; ks<8; ks++){
                    uint32_t bb[2];
                    bb[0] = __float_as_uint(kr[4*((2*ks  ) ^ g) + tg]);
                    bb[1] = __float_as_uint(kr[4*((2*ks+1) ^ g) + tg]);
                    mma8(s[j], aq[ks], bb);
                }
            }

            #pragma unroll
            for(int j=0;j<CNT;j++){
                int c = 8*(BASE+j) + 2*tg;
                float2 bv0 = *(const float2*)(b0p + c);
                float2 bv1 = *(const float2*)(b1p + c);
                s[j][0] += bv0.x; s[j][1] += bv0.y;
                s[j][2] += bv1.x; s[j][3] += bv1.y;
                if(c   >= SEQ){ s[j][0] = -1e30f; s[j][2] = -1e30f; }
                if(c+1 >= SEQ){ s[j][1] = -1e30f; s[j][3] = -1e30f; }
            }

            float mc0 = -1e30f, mc1 = -1e30f;
            #pragma unroll
            for(int j=0;j<CNT;j++){
                mc0 = fmaxf(mc0, fmaxf(s[j][0], s[j][1]));
                mc1 = fmaxf(mc1, fmaxf(s[j][2], s[j][3]));
            }
            #pragma unroll
            for(int off=1;off<4;off<<=1){
                mc0 = fmaxf(mc0, __shfl_xor_sync(0xffffffffu, mc0, off));
                mc1 = fmaxf(mc1, __shfl_xor_sync(0xffffffffu, mc1, off));
            }
            float mn0 = fmaxf(m0, mc0), mn1 = fmaxf(m1, mc1);
            float sc0 = __expf(m0 - mn0), sc1 = __expf(m1 - mn1);
            m0 = mn0; m1 = mn1;
            z0 *= sc0; z1 *= sc1;
            #pragma unroll
            for(int nt=0;nt<8;nt++){
                o[nt][0] *= sc0; o[nt][1] *= sc0;
                o[nt][2] *= sc1; o[nt][3] *= sc1;
            }
            #pragma unroll
            for(int j=0;j<CNT;j++){
                s[j][0] = __expf(s[j][0] - m0);
                s[j][1] = __expf(s[j][1] - m0);
                s[j][2] = __expf(s[j][2] - m1);
                s[j][3] = __expf(s[j][3] - m1);
                z0 += s[j][0] + s[j][1];
                z1 += s[j][2] + s[j][3];
            }

            #pragma unroll
            for(int j=0;j<CNT;j++){
                const int ks = BASE + j;
                float* buf = myP + (ks & 1) * (16*PBP);
                *(float2*)(buf + g*PBP     + 2*tg) = make_float2(f2tf(s[j][0]), f2tf(s[j][1]));
                *(float2*)(buf + (g+8)*PBP + 2*tg) = make_float2(f2tf(s[j][2]), f2tf(s[j][3]));
                __syncwarp();
                uint32_t a[4];
                a[0] = __float_as_uint(buf[g*PBP     + tg    ]);
                a[1] = __float_as_uint(buf[(g+8)*PBP + tg    ]);
                a[2] = __float_as_uint(buf[g*PBP     + tg + 4]);
                a[3] = __float_as_uint(buf[(g+8)*PBP + tg + 4]);
                #pragma unroll
                for(int nt=0; nt<8; nt++){
                    const float* vr = Vt + (8*nt + g)*SP + 8*ks;
                    uint32_t bb[2];
                    bb[0] = __float_as_uint(vr[tg    ]);
                    bb[1] = __float_as_uint(vr[tg + 4]);
                    mma8(o[nt], a, bb);
                }
            }
        }

        #pragma unroll
        for(int off=1;off<4;off<<=1){
            z0 += __shfl_xor_sync(0xffffffffu, z0, off);
            z1 += __shfl_xor_sync(0xffffffffu, z1, off);
        }
        const float inv0 = 1.0f / z0, inv1 = 1.0f / z1;

        #pragma unroll
        for(int nt=0; nt<8; nt++){
            int c = h*HD + 8*nt + 2*tg;
            if(row0 < SEQ)
                *(float2*)(out + (size_t)(b*SEQ + row0)*HID + c) =
                    make_float2(o[nt][0]*inv0, o[nt][1]*inv0);
            if(row1 < SEQ)
                *(float2*)(out + (size_t)(b*SEQ + row1)*HID + c) =
                    make_float2(o[nt][2]*inv1, o[nt][3]*inv1);
        }
    }
}

// ---------------- launch ------------------------------------------------------
extern "C" void kernel_launch(void* const* d_in, const int* in_sizes, int n_in,
                              void* d_out, int out_size){
    const float* hs    = (const float*)d_in[0];
    const float* wq    = (const float*)d_in[1];
    const float* bq    = (const float*)d_in[2];
    const float* wk    = (const float*)d_in[3];
    const float* wv    = (const float*)d_in[4];
    const float* bv    = (const float*)d_in[5];
    const float* table = (const float*)d_in[6];

    float *q, *k, *v, *bias, *atf, *wtf;
    cudaGetSymbolAddress((void**)&q,    g_q);
    cudaGetSymbolAddress((void**)&k,    g_k);
    cudaGetSymbolAddress((void**)&v,    g_v);
    cudaGetSymbolAddress((void**)&bias, g_bias);
    cudaGetSymbolAddress((void**)&atf,  g_atf);
    cudaGetSymbolAddress((void**)&wtf,  g_wtf);

    cudaFuncSetAttribute(attention, cudaFuncAttributeMaxDynamicSharedMemorySize, ATTN_SMEM);
    cudaFuncSetAttribute(qkv_gemm,  cudaFuncAttributeMaxDynamicSharedMemorySize, GEMM_SMEM);

    const int a4 = MTOT*HID/4, w4 = HID*HID/4;
    conv_tf32<<<(a4 + 255)/256, 256>>>(hs, atf, a4);
    conv_tf32<<<(w4 + 255)/256, 256>>>(wq, wtf,             w4);
    conv_tf32<<<(w4 + 255)/256, 256>>>(wk, wtf +   HID*HID, w4);
    conv_tf32<<<(w4 + 255)/256, 256>>>(wv, wtf + 2*HID*HID, w4);

    build_bias<<<(SEQ*SEQ + 255) / 256, 256>>>(table, bias);

    dim3 gg((MTOT + BM - 1) / BM, HID / BN, 3);   // 99 x 6 x 3
    qkv_gemm<<<gg, 256, GEMM_SMEM>>>(bq, bv);

    attention<<<BATCH*NHEAD, 512, ATTN_SMEM>>>(q, k, v, bias, (float*)d_out);
}